// round 15
// baseline (speedup 1.0000x reference)
#include <cuda_runtime.h>
#include <cuda_bf16.h>
#include <math.h>
#include <stdint.h>

#define BB 512
#define HID 512
#define NC 9
#define SL 64
#define L1 35
#define G3 1536
#define JAX_PARTITIONABLE 1

// ---------------- device scratch (no allocations allowed) -------------------
__device__ float g_y1t[BB * L1 * HID];
__device__ float g_Xseq[SL * BB * 256];
__device__ float g_Gx[(size_t)SL * BB * G3];
__device__ float g_W1cat[128 * 1024];
__device__ float g_W2cat[1024 * 512];
__device__ float g_W3[272 * G3];
__device__ float g_Wo[G3 * NC];
__device__ float g_Wrec[3 * 512 * G3];
__device__ float g_brec[3 * G3];
__device__ float g_SkelP[SL * BB * 16];
__device__ float g_bn1s[HID], g_bn1sh[HID];
__device__ float g_bn2s[256], g_bn2sh[256];
__device__ float g_h1[BB * HID], g_h2[BB * HID], g_out[BB * NC];
__device__ float g_gh1[BB * G3], g_gi2[BB * G3], g_gh2[BB * G3];

// ---------------- packed f32x2 + cp.async helpers ---------------------------
__device__ __forceinline__ unsigned long long dupf2(float a) {
    unsigned long long r;
    asm("mov.b64 %0, {%1, %1};" : "=l"(r) : "f"(a));
    return r;
}
__device__ __forceinline__ void ffma2(unsigned long long& c, unsigned long long a,
                                      unsigned long long b) {
    asm("fma.rn.f32x2 %0, %1, %2, %0;" : "+l"(c) : "l"(a), "l"(b));
}
__device__ __forceinline__ void unpackf2(unsigned long long v, float& lo, float& hi) {
    asm("mov.b64 {%0, %1}, %2;" : "=f"(lo), "=f"(hi) : "l"(v));
}
__device__ __forceinline__ uint32_t smem_u32(const void* p) {
    uint32_t a;
    asm("{ .reg .u64 t; cvta.to.shared.u64 t, %1; cvt.u32.u64 %0, t; }" : "=r"(a) : "l"(p));
    return a;
}
__device__ __forceinline__ void cpa16(uint32_t s, const void* g) {
    asm volatile("cp.async.cg.shared.global [%0], [%1], 16;" :: "r"(s), "l"(g));
}
#define CP_COMMIT() asm volatile("cp.async.commit_group;" ::: "memory")
#define CP_WAIT0()  asm volatile("cp.async.wait_group 0;" ::: "memory")

// ---------------- threefry2x32-20 (bit-exact JAX) ---------------------------
__device__ __forceinline__ unsigned rotl32(unsigned v, int d) {
    return (v << d) | (v >> (32 - d));
}
__device__ __forceinline__ void tf2x32(unsigned k0, unsigned k1, unsigned x0, unsigned x1,
                                       unsigned& o0, unsigned& o1) {
    unsigned ks2 = 0x1BD11BDAu ^ k0 ^ k1;
    x0 += k0; x1 += k1;
#define TFR(r) { x0 += x1; x1 = rotl32(x1, (r)); x1 ^= x0; }
    TFR(13) TFR(15) TFR(26) TFR(6)
    x0 += k1; x1 += ks2 + 1u;
    TFR(17) TFR(29) TFR(16) TFR(24)
    x0 += ks2; x1 += k0 + 2u;
    TFR(13) TFR(15) TFR(26) TFR(6)
    x0 += k0; x1 += k1 + 3u;
    TFR(17) TFR(29) TFR(16) TFR(24)
    x0 += k1; x1 += ks2 + 4u;
    TFR(13) TFR(15) TFR(26) TFR(6)
    x0 += ks2; x1 += k0 + 5u;
#undef TFR
    o0 = x0; o1 = x1;
}
__device__ __forceinline__ float jax_uniform_r(int t, int i) {
    unsigned bits;
#if JAX_PARTITIONABLE
    unsigned k0, k1, o0, o1;
    tf2x32(0u, 42u, 0u, (unsigned)t, k0, k1);
    tf2x32(k0, k1, 0u, (unsigned)i, o0, o1);
    bits = o0 ^ o1;
#else
    unsigned k0, k1, a, b;
    {
        int j0 = 2 * t, j1 = 2 * t + 1;
        if (j0 < SL) { tf2x32(0u, 42u, (unsigned)j0, (unsigned)(j0 + SL), a, b); k0 = a; }
        else         { tf2x32(0u, 42u, (unsigned)(j0 - SL), (unsigned)j0, a, b); k0 = b; }
        if (j1 < SL) { tf2x32(0u, 42u, (unsigned)j1, (unsigned)(j1 + SL), a, b); k1 = a; }
        else         { tf2x32(0u, 42u, (unsigned)(j1 - SL), (unsigned)j1, a, b); k1 = b; }
    }
    const int half = (BB * NC) / 2;
    if (i < half) { tf2x32(k0, k1, (unsigned)i, (unsigned)(i + half), a, b); bits = a; }
    else          { tf2x32(k0, k1, (unsigned)(i - half), (unsigned)i, a, b); bits = b; }
#endif
    return __uint_as_float((bits >> 9) | 0x3F800000u) - 1.0f;
}

// ---------------- prep ------------------------------------------------------
__global__ void k_prep(const float* __restrict__ ct1w, const float* __restrict__ ct1b,
                       const float* __restrict__ bn1g, const float* __restrict__ bn1b,
                       const float* __restrict__ bn1m, const float* __restrict__ bn1v,
                       const float* __restrict__ ct2w, const float* __restrict__ ct2b,
                       const float* __restrict__ bn2g, const float* __restrict__ bn2b,
                       const float* __restrict__ bn2m, const float* __restrict__ bn2v,
                       const float* __restrict__ wih1, const float* __restrict__ skel,
                       const float* __restrict__ whh1, const float* __restrict__ bhh1,
                       const float* __restrict__ wih2, const float* __restrict__ bih2,
                       const float* __restrict__ whh2, const float* __restrict__ bhh2) {
    const int nW1 = 128 * 1024, nW2 = 1024 * 512, nW3 = 272 * G3, nWo = G3 * NC;
    const int nWrec = 3 * 512 * G3, nBrec = 3 * G3;
    const int nSk = SL * BB * 16, nB1 = HID, nB2 = 256, nOut = BB * NC;
    int idx = blockIdx.x * blockDim.x + threadIdx.x;
    int r = idx;
    if (r < nW1) {
        int k = r >> 10, n = r & 1023;
        int c = k & 63, o = n & 511, par = n >> 9;
        int t = (k < 64) ? par : par + 2;
        g_W1cat[r] = ct1w[(c * 512 + o) * 4 + t];
        return;
    }
    r -= nW1;
    if (r < nW2) {
        int k = r >> 9, n = r & 511;
        int c = k & 511, o = n & 255, par = n >> 8;
        int t = (k < 512) ? par : par + 2;
        g_W2cat[r] = ct2w[(c * 256 + o) * 4 + t];
        return;
    }
    r -= nW2;
    if (r < nW3) {
        int k = r / G3, j = r % G3;
        float v = 0.f;
        if (k < 256)      v = wih1[j * 274 + 9 + k];
        else if (k < 265) v = wih1[j * 274 + 265 + (k - 256)];
        g_W3[r] = v;
        return;
    }
    r -= nW3;
    if (r < nWo) { g_Wo[r] = wih1[(r / 9) * 274 + (r % 9)]; return; }
    r -= nWo;
    if (r < nWrec) {
        int z = r / (512 * G3), rem = r % (512 * G3);
        int k = rem / G3, n = rem % G3;
        const float* src = (z == 0) ? whh1 : (z == 1 ? wih2 : whh2);
        g_Wrec[r] = src[n * 512 + k];
        return;
    }
    r -= nWrec;
    if (r < nBrec) {
        int z = r / G3, n = r % G3;
        const float* src = (z == 0) ? bhh1 : (z == 1 ? bih2 : bhh2);
        g_brec[r] = src[n];
        return;
    }
    r -= nBrec;
    if (r < nSk) {
        int row = r >> 4, c = r & 15;
        int t = row >> 9, b = row & 511;
        g_SkelP[r] = (c < NC) ? skel[b * (SL * NC) + t * NC + c] : 0.f;
        return;
    }
    r -= nSk;
    if (r < nB1) {
        float s = bn1g[r] * rsqrtf(bn1v[r] + 1e-5f);
        g_bn1s[r] = s;
        g_bn1sh[r] = s * (ct1b[r] - bn1m[r]) + bn1b[r];
        return;
    }
    r -= nB1;
    if (r < nB2) {
        float s = bn2g[r] * rsqrtf(bn2v[r] + 1e-5f);
        g_bn2s[r] = s;
        g_bn2sh[r] = s * (ct2b[r] - bn2m[r]) + bn2b[r];
        return;
    }
    r -= nB2;
    if (r < nOut) g_out[r] = 0.f;
}

// ------------- small GEMM (hfc only): 64x128 tile, 4x8 micro, NT ------------
__global__ __launch_bounds__(256) void k_gemm_nt(
    const float* __restrict__ A, const float* __restrict__ W,
    const float* __restrict__ bias, float* __restrict__ C, int K, int N) {
    __shared__ float As[16][64];
    __shared__ float Ws[16][128];
    int tid = threadIdx.x;
    int tx = tid & 15, ty = tid >> 4;
    int n0 = blockIdx.x * 128, m0 = blockIdx.y * 64;
    float acc[4][8];
#pragma unroll
    for (int i = 0; i < 4; i++)
#pragma unroll
        for (int j = 0; j < 8; j++) acc[i][j] = 0.f;
    for (int k0 = 0; k0 < K; k0 += 16) {
        int arow = tid >> 2, kq = (tid & 3) << 2;
        float4 v = *(const float4*)(A + (size_t)(m0 + arow) * K + k0 + kq);
        As[kq][arow] = v.x; As[kq + 1][arow] = v.y;
        As[kq + 2][arow] = v.z; As[kq + 3][arow] = v.w;
        int nrow = tid >> 1, h = tid & 1;
#pragma unroll
        for (int i = 0; i < 2; i++) {
            int kk = h * 8 + i * 4;
            float4 w = *(const float4*)(W + (size_t)(n0 + nrow) * K + k0 + kk);
            Ws[kk][nrow] = w.x; Ws[kk + 1][nrow] = w.y;
            Ws[kk + 2][nrow] = w.z; Ws[kk + 3][nrow] = w.w;
        }
        __syncthreads();
#pragma unroll
        for (int k = 0; k < 16; k++) {
            float a[4], w[8];
            *(float4*)a = *(const float4*)&As[k][ty * 4];
            *(float4*)w = *(const float4*)&Ws[k][tx * 8];
            *(float4*)(w + 4) = *(const float4*)&Ws[k][tx * 8 + 4];
#pragma unroll
            for (int i = 0; i < 4; i++)
#pragma unroll
                for (int j = 0; j < 8; j++) acc[i][j] += a[i] * w[j];
        }
        __syncthreads();
    }
#pragma unroll
    for (int i = 0; i < 4; i++) {
        int rg = m0 + ty * 4 + i;
#pragma unroll
        for (int j = 0; j < 8; j++) {
            int n = n0 + tx * 8 + j;
            C[(size_t)rg * N + n] = acc[i][j] + bias[n];
        }
    }
}

// ------------- big prep GEMM: 64x128 tile, 8x8 micro, cp.async W ------------
__device__ __forceinline__ void g2_loadA(const float* A, int K, int amode, int gz,
                                         int m0, int arow, int ak, int k0, float ra[8]) {
    int rg = m0 + arow;
    if (amode == 1) {
#pragma unroll
        for (int i = 0; i < 8; i++) {
            int k = k0 + ak + i;
            int tap = k >> 6, c = k & 63, ii = gz - tap;
            ra[i] = (ii >= 0 && ii < 16) ? A[rg * 1024 + c * 16 + ii] : 0.f;
        }
    } else if (amode == 2) {
        int k = k0 + ak;
        int tap = k >> 9, c = k & 511, ii = gz - tap;
        if (ii >= 0) {
            const float* p = g_y1t + ((size_t)rg * L1 + ii) * 512 + c;
            float4 a0 = *(const float4*)p, a1 = *(const float4*)(p + 4);
            ra[0] = a0.x; ra[1] = a0.y; ra[2] = a0.z; ra[3] = a0.w;
            ra[4] = a1.x; ra[5] = a1.y; ra[6] = a1.z; ra[7] = a1.w;
        } else {
#pragma unroll
            for (int i = 0; i < 8; i++) ra[i] = 0.f;
        }
    } else {
        int k = k0 + ak;
        const float* p = (k < 256) ? (g_Xseq + (size_t)rg * 256 + k)
                                   : (g_SkelP + (size_t)rg * 16 + (k - 256));
        float4 a0 = *(const float4*)p, a1 = *(const float4*)(p + 4);
        ra[0] = a0.x; ra[1] = a0.y; ra[2] = a0.z; ra[3] = a0.w;
        ra[4] = a1.x; ra[5] = a1.y; ra[6] = a1.z; ra[7] = a1.w;
    }
}
__global__ __launch_bounds__(128, 4) void k_gemm2(
    const float* __restrict__ A, const float* __restrict__ W,
    const float* __restrict__ bias, float* __restrict__ C,
    int K, int N, int amode, int emode) {
    __shared__ float As[2][16][68];
    __shared__ float Ws[2][16][128];
    int tid = threadIdx.x;
    int tx = tid & 15, ty = tid >> 4;
    int n0 = blockIdx.x * 128, m0 = blockIdx.y * 64, gz = blockIdx.z;

    unsigned long long acc2[8][4];
#pragma unroll
    for (int i = 0; i < 8; i++)
#pragma unroll
        for (int jp = 0; jp < 4; jp++) acc2[i][jp] = 0ULL;

    int arow = tid >> 1, ak = (tid & 1) * 8;
    int wk = tid >> 4, wn = (tid & 15) * 8;
    float ra[8];
    int nk = K >> 4;
    const uint32_t ws0 = smem_u32(&Ws[0][wk][wn]);
    const uint32_t ws1 = smem_u32(&Ws[1][wk][wn]);
    const float* wbase0 = W + (size_t)wk * N + n0 + wn;
    const float* wbase1 = W + (size_t)(wk + 8) * N + n0 + wn;

#define G2_ISSUEW(k0, buf)                                                        \
    {                                                                             \
        uint32_t s = (buf) ? ws1 : ws0;                                           \
        const float* p0 = wbase0 + (size_t)(k0) * N;                              \
        const float* p1 = wbase1 + (size_t)(k0) * N;                              \
        cpa16(s, p0); cpa16(s + 16, p0 + 4);                                      \
        cpa16(s + 4096, p1); cpa16(s + 4096 + 16, p1 + 4);                        \
        CP_COMMIT();                                                              \
    }
#define G2_STOREA(buf)                                                            \
    {                                                                             \
        _Pragma("unroll")                                                         \
        for (int i = 0; i < 8; i++) As[buf][ak + i][arow] = ra[i];                \
    }

    G2_ISSUEW(0, 0)
    g2_loadA(A, K, amode, gz, m0, arow, ak, 0, ra);
    G2_STOREA(0)
    CP_WAIT0();
    __syncthreads();

    for (int it = 0; it < nk; it++) {
        int cur = it & 1;
        bool more = (it + 1 < nk);
        if (more) {
            G2_ISSUEW((it + 1) << 4, cur ^ 1)
            g2_loadA(A, K, amode, gz, m0, arow, ak, (it + 1) << 4, ra);
        }
#pragma unroll
        for (int k = 0; k < 16; k++) {
            float a[8];
            *(float4*)a = *(const float4*)&As[cur][k][ty * 8];
            *(float4*)(a + 4) = *(const float4*)&As[cur][k][ty * 8 + 4];
            const ulonglong2* wp2 = (const ulonglong2*)&Ws[cur][k][tx * 8];
            ulonglong2 p0 = wp2[0], p1 = wp2[1];
            unsigned long long w2[4] = {p0.x, p0.y, p1.x, p1.y};
#pragma unroll
            for (int i = 0; i < 8; i++) {
                unsigned long long aa = dupf2(a[i]);
#pragma unroll
                for (int jp = 0; jp < 4; jp++) ffma2(acc2[i][jp], aa, w2[jp]);
            }
        }
        if (more) G2_STOREA(cur ^ 1)
        CP_WAIT0();
        __syncthreads();
    }
#undef G2_ISSUEW
#undef G2_STOREA

#pragma unroll
    for (int i = 0; i < 8; i++) {
        int rg = m0 + ty * 8 + i;
        float av[8];
#pragma unroll
        for (int jp = 0; jp < 4; jp++) unpackf2(acc2[i][jp], av[2 * jp], av[2 * jp + 1]);
#pragma unroll
        for (int j = 0; j < 8; j++) {
            int n = n0 + tx * 8 + j;
            float v = av[j];
            if (emode == 0) {
                C[(size_t)rg * N + n] = v + bias[n];
            } else if (emode == 1) {
                int par = n >> 9, o = n & 511, l = 2 * gz + par;
                if (l < L1) {
                    float y = g_bn1s[o] * v + g_bn1sh[o];
                    g_y1t[((size_t)rg * L1 + l) * 512 + o] = (y >= 0.f) ? y : 0.2f * y;
                }
            } else {
                int par = n >> 8, o = n & 255, l = 2 * gz + par;
                float y = g_bn2s[o] * v + g_bn2sh[o];
                g_Xseq[((size_t)l * BB + rg) * 256 + o] = (y >= 0.f) ? y : 0.2f * y;
            }
        }
    }
}

// ------------- loop GEMM: z=0..2 recurrence, z=3 Gx chunk for step t+1 ------
__global__ __launch_bounds__(128, 4) void k_rec(const float* __restrict__ bih1, int t) {
    __shared__ float As[2][16][68];
    __shared__ float Ws[2][16][128];
    int tid = threadIdx.x;
    int tx = tid & 15, ty = tid >> 4;
    int n0 = blockIdx.x * 128, m0 = blockIdx.y * 64, gz = blockIdx.z;

    const float* A; const float* W; const float* bias; float* C;
    int nk;
    size_t growb = 0;   // extra row offset for Gx rows (amode-3 addressing)
    if (gz < 3) {
        A = (gz == 2) ? g_h2 : g_h1;
        W = g_Wrec + (size_t)gz * 512 * G3;
        bias = g_brec + gz * G3;
        C = (gz == 0) ? g_gh1 : (gz == 1 ? g_gi2 : g_gh2);
        nk = 32;
    } else {
        A = nullptr;
        W = g_W3;
        bias = bih1;
        growb = (size_t)(t + 1) * 512;
        C = g_Gx + growb * G3;
        nk = 17;   // K = 272
    }

    unsigned long long acc2[8][4];
#pragma unroll
    for (int i = 0; i < 8; i++)
#pragma unroll
        for (int jp = 0; jp < 4; jp++) acc2[i][jp] = 0ULL;

    int arow = tid >> 1, ak = (tid & 1) * 8;
    int wk = tid >> 4, wn = (tid & 15) * 8;
    float ra[8];
    const uint32_t ws0 = smem_u32(&Ws[0][wk][wn]);
    const uint32_t ws1 = smem_u32(&Ws[1][wk][wn]);
    const float* wbase0 = W + (size_t)wk * G3 + n0 + wn;
    const float* wbase1 = W + (size_t)(wk + 8) * G3 + n0 + wn;
    const float* abase = (gz < 3) ? (A + (size_t)(m0 + arow) * 512 + ak) : nullptr;
    const size_t grow = growb + m0 + arow;

#define R_ISSUEW(k0, buf)                                                         \
    {                                                                             \
        uint32_t s = (buf) ? ws1 : ws0;                                           \
        const float* p0 = wbase0 + (size_t)(k0) * G3;                             \
        const float* p1 = wbase1 + (size_t)(k0) * G3;                             \
        cpa16(s, p0); cpa16(s + 16, p0 + 4);                                      \
        cpa16(s + 4096, p1); cpa16(s + 4096 + 16, p1 + 4);                        \
        CP_COMMIT();                                                              \
    }
#define R_LOADA(k0)                                                               \
    {                                                                             \
        if (gz < 3) {                                                             \
            float4 a0 = *(const float4*)(abase + (k0));                           \
            float4 a1 = *(const float4*)(abase + (k0) + 4);                       \
            ra[0] = a0.x; ra[1] = a0.y; ra[2] = a0.z; ra[3] = a0.w;               \
            ra[4] = a1.x; ra[5] = a1.y; ra[6] = a1.z; ra[7] = a1.w;               \
        } else {                                                                  \
            int k = (k0) + ak;                                                    \
            const float* p = (k < 256) ? (g_Xseq + grow * 256 + k)                \
                                       : (g_SkelP + grow * 16 + (k - 256));      \
            float4 a0 = *(const float4*)p, a1 = *(const float4*)(p + 4);          \
            ra[0] = a0.x; ra[1] = a0.y; ra[2] = a0.z; ra[3] = a0.w;               \
            ra[4] = a1.x; ra[5] = a1.y; ra[6] = a1.z; ra[7] = a1.w;               \
        }                                                                         \
    }
#define R_STOREA(buf)                                                             \
    {                                                                             \
        _Pragma("unroll")                                                         \
        for (int i = 0; i < 8; i++) As[buf][ak + i][arow] = ra[i];                \
    }

    R_ISSUEW(0, 0)
    R_LOADA(0)
    R_STOREA(0)
    CP_WAIT0();
    __syncthreads();

    for (int it = 0; it < nk; it++) {
        int cur = it & 1;
        bool more = (it + 1 < nk);
        if (more) {
            R_ISSUEW((it + 1) << 4, cur ^ 1)
            R_LOADA((it + 1) << 4)
        }
#pragma unroll
        for (int k = 0; k < 16; k++) {
            float a[8];
            *(float4*)a = *(const float4*)&As[cur][k][ty * 8];
            *(float4*)(a + 4) = *(const float4*)&As[cur][k][ty * 8 + 4];
            const ulonglong2* wp2 = (const ulonglong2*)&Ws[cur][k][tx * 8];
            ulonglong2 p0 = wp2[0], p1 = wp2[1];
            unsigned long long w2[4] = {p0.x, p0.y, p1.x, p1.y};
#pragma unroll
            for (int i = 0; i < 8; i++) {
                unsigned long long aa = dupf2(a[i]);
#pragma unroll
                for (int jp = 0; jp < 4; jp++) ffma2(acc2[i][jp], aa, w2[jp]);
            }
        }
        if (more) R_STOREA(cur ^ 1)
        CP_WAIT0();
        __syncthreads();
    }
#undef R_ISSUEW
#undef R_LOADA
#undef R_STOREA

#pragma unroll
    for (int i = 0; i < 8; i++) {
        int rg = m0 + ty * 8 + i;
        float av[8];
#pragma unroll
        for (int jp = 0; jp < 4; jp++) unpackf2(acc2[i][jp], av[2 * jp], av[2 * jp + 1]);
        float* cp = C + (size_t)rg * G3 + n0 + tx * 8;
        const float* bp = bias + n0 + tx * 8;
#pragma unroll
        for (int j = 0; j < 8; j++) cp[j] = av[j] + bp[j];
    }
}

// ---------------- GRU1 gates (standalone, only for t=0) ---------------------
__global__ __launch_bounds__(512) void k_gates1(int t) {
    __shared__ float os[NC];
    int b = blockIdx.x, j = threadIdx.x;
    if (j < NC) os[j] = g_out[b * NC + j];
    __syncthreads();
    size_t base = ((size_t)t * BB + b) * G3;
    float gi[3], gh[3];
#pragma unroll
    for (int s = 0; s < 3; s++) {
        int jj = j + s * 512;
        float v = g_Gx[base + jj];
        const float* wo = g_Wo + jj * NC;
#pragma unroll
        for (int c = 0; c < NC; c++) v += os[c] * wo[c];
        gi[s] = v;
        gh[s] = g_gh1[b * G3 + jj];
    }
    float h = g_h1[b * 512 + j];
    float rr = 1.f / (1.f + expf(-(gi[0] + gh[0])));
    float zz = 1.f / (1.f + expf(-(gi[1] + gh[1])));
    float nn = tanhf(gi[2] + rr * gh[2]);
    float hn = (1.f - zz) * nn + zz * h;
    g_h1[b * 512 + j] = hn;
    if (t == 0) g_h2[b * 512 + j] = hn;
}

// ------- fused: GRU2(t) + logits + sample + GRU1(t+1) -----------------------
__global__ __launch_bounds__(512) void k_gates21(const float* __restrict__ nfcw,
                                                 const float* __restrict__ nfcb,
                                                 float* __restrict__ out, int t) {
    __shared__ float hs[512];
    __shared__ float os[NC];
    int b = blockIdx.x, j = threadIdx.x;
    float h = g_h2[b * 512 + j];
    float ir = g_gi2[b * G3 + j], iz = g_gi2[b * G3 + 512 + j], in = g_gi2[b * G3 + 1024 + j];
    float hr = g_gh2[b * G3 + j], hz = g_gh2[b * G3 + 512 + j], hn2 = g_gh2[b * G3 + 1024 + j];
    float rr = 1.f / (1.f + expf(-(ir + hr)));
    float zz = 1.f / (1.f + expf(-(iz + hz)));
    float nn = tanhf(in + rr * hn2);
    float hnew = (1.f - zz) * nn + zz * h;
    g_h2[b * 512 + j] = hnew;
    hs[j] = hnew;
    __syncthreads();
    int w = j >> 5, lane = j & 31;
    if (w < NC) {
        float s = 0.f;
        for (int q = lane; q < 512; q += 32) s += hs[q] * nfcw[w * 512 + q];
#pragma unroll
        for (int o = 16; o; o >>= 1) s += __shfl_down_sync(0xffffffffu, s, o);
        if (lane == 0) {
            float l = s + nfcb[w];
            out[(size_t)b * (SL * NC) + t * NC + w] = l;
            float sg = 1.f / (1.f + expf(-l));
            float r = jax_uniform_r(t, b * NC + w);
            os[w] = (sg - r > 0.f) ? 1.f : 0.f;
        }
    }
    __syncthreads();
    if (t + 1 < SL) {
        size_t base = ((size_t)(t + 1) * BB + b) * G3;
        float gi[3], gh[3];
#pragma unroll
        for (int s = 0; s < 3; s++) {
            int jj = j + s * 512;
            float v = g_Gx[base + jj];
            const float* wo = g_Wo + jj * NC;
#pragma unroll
            for (int c = 0; c < NC; c++) v += os[c] * wo[c];
            gi[s] = v;
            gh[s] = g_gh1[b * G3 + jj];
        }
        float h1 = g_h1[b * 512 + j];
        float r1 = 1.f / (1.f + expf(-(gi[0] + gh[0])));
        float z1 = 1.f / (1.f + expf(-(gi[1] + gh[1])));
        float n1 = tanhf(gi[2] + r1 * gh[2]);
        g_h1[b * 512 + j] = (1.f - z1) * n1 + z1 * h1;
    }
}

// ---------------- host ------------------------------------------------------
extern "C" void kernel_launch(void* const* d_in, const int* in_sizes, int n_in,
                              void* d_out, int out_size) {
    int ofs = (n_in >= 30) ? 0 : -2;
    const float* qz   = (const float*)d_in[0];
    const float* skel = (const float*)d_in[2];
    const float* se   = (const float*)d_in[3];
    const float* ct1w = (const float*)d_in[6 + ofs];
    const float* ct1b = (const float*)d_in[7 + ofs];
    const float* bn1g = (const float*)d_in[8 + ofs];
    const float* bn1b = (const float*)d_in[9 + ofs];
    const float* bn1m = (const float*)d_in[10 + ofs];
    const float* bn1v = (const float*)d_in[11 + ofs];
    const float* ct2w = (const float*)d_in[12 + ofs];
    const float* ct2b = (const float*)d_in[13 + ofs];
    const float* bn2g = (const float*)d_in[14 + ofs];
    const float* bn2b = (const float*)d_in[15 + ofs];
    const float* bn2m = (const float*)d_in[16 + ofs];
    const float* bn2v = (const float*)d_in[17 + ofs];
    const float* hfcw = (const float*)d_in[18 + ofs];
    const float* hfcb = (const float*)d_in[19 + ofs];
    const float* wih1 = (const float*)d_in[20 + ofs];
    const float* whh1 = (const float*)d_in[21 + ofs];
    const float* bih1 = (const float*)d_in[22 + ofs];
    const float* bhh1 = (const float*)d_in[23 + ofs];
    const float* wih2 = (const float*)d_in[24 + ofs];
    const float* whh2 = (const float*)d_in[25 + ofs];
    const float* bih2 = (const float*)d_in[26 + ofs];
    const float* bhh2 = (const float*)d_in[27 + ofs];
    const float* nfcw = (const float*)d_in[28 + ofs];
    const float* nfcb = (const float*)d_in[29 + ofs];
    float* out = (float*)d_out;

    float *pW1, *pW2, *pW3, *pGx, *pH1;
    cudaGetSymbolAddress((void**)&pW1, g_W1cat);
    cudaGetSymbolAddress((void**)&pW2, g_W2cat);
    cudaGetSymbolAddress((void**)&pW3, g_W3);
    cudaGetSymbolAddress((void**)&pGx, g_Gx);
    cudaGetSymbolAddress((void**)&pH1, g_h1);

    const int TOTAL = 128 * 1024 + 1024 * 512 + 272 * G3 + G3 * NC +
                      3 * 512 * G3 + 3 * G3 +
                      SL * BB * 16 + HID + 256 + BB * NC;
    k_prep<<<(TOTAL + 255) / 256, 256>>>(ct1w, ct1b, bn1g, bn1b, bn1m, bn1v,
                                         ct2w, ct2b, bn2g, bn2b, bn2m, bn2v,
                                         wih1, skel,
                                         whh1, bhh1, wih2, bih2, whh2, bhh2);
    k_gemm_nt<<<dim3(4, 8, 1), 256>>>(se, hfcw, hfcb, pH1, 512, 512);
    k_gemm2<<<dim3(8, 8, 18), 128>>>(qz, pW1, nullptr, nullptr, 128, 1024, 1, 1);
    k_gemm2<<<dim3(4, 8, 32), 128>>>(nullptr, pW2, nullptr, nullptr, 1024, 512, 2, 2);
    // Gx chunk for t=0 only (rows 0..511); rest computed inside the loop
    k_gemm2<<<dim3(12, 8, 1), 128>>>(nullptr, pW3, bih1, pGx, 272, G3, 3, 0);
    k_rec<<<dim3(12, 8, 1), 128>>>(bih1, 0);   // gh1(0) (z=0 only)
    k_gates1<<<BB, 512>>>(0);                  // GRU1 step 0

    for (int t = 0; t < SL; t++) {
        // z=0..2: gh1(t+1)/gi2(t)/gh2(t); z=3: Gx chunk for step t+1
        int nz = (t + 1 < SL) ? 4 : 3;
        k_rec<<<dim3(12, 8, nz), 128>>>(bih1, t);
        k_gates21<<<BB, 512>>>(nfcw, nfcb, out, t);
    }
}

// round 16
// speedup vs baseline: 1.2313x; 1.2313x over previous
#include <cuda_runtime.h>
#include <cuda_bf16.h>
#include <math.h>
#include <stdint.h>

#define BB 512
#define HID 512
#define NC 9
#define SL 64
#define L1 35
#define G3 1536
#define JAX_PARTITIONABLE 1

// ---------------- device scratch (no allocations allowed) -------------------
__device__ float g_y1t[BB * L1 * HID];
__device__ float g_Xseq[SL * BB * 256];
__device__ float g_Gx[(size_t)SL * BB * G3];
__device__ float g_W1cat[128 * 1024];
__device__ float g_W2cat[1024 * 512];
__device__ float g_W3[272 * G3];
__device__ float g_Wo[G3 * NC];
__device__ float g_Wrec[3 * 512 * G3];
__device__ float g_brec[3 * G3];
__device__ float g_SkelP[SL * BB * 16];
__device__ float g_bn1s[HID], g_bn1sh[HID];
__device__ float g_bn2s[256], g_bn2sh[256];
__device__ float g_h1[BB * HID], g_h2[BB * HID], g_out[BB * NC];
__device__ float g_h1T[HID * BB], g_h2T[HID * BB];   // transposed [j][b]
__device__ float g_gh1[BB * G3], g_gi2[BB * G3], g_gh2[BB * G3];

// ---------------- packed f32x2 + cp.async helpers ---------------------------
__device__ __forceinline__ unsigned long long dupf2(float a) {
    unsigned long long r;
    asm("mov.b64 %0, {%1, %1};" : "=l"(r) : "f"(a));
    return r;
}
__device__ __forceinline__ void ffma2(unsigned long long& c, unsigned long long a,
                                      unsigned long long b) {
    asm("fma.rn.f32x2 %0, %1, %2, %0;" : "+l"(c) : "l"(a), "l"(b));
}
__device__ __forceinline__ void unpackf2(unsigned long long v, float& lo, float& hi) {
    asm("mov.b64 {%0, %1}, %2;" : "=f"(lo), "=f"(hi) : "l"(v));
}
__device__ __forceinline__ uint32_t smem_u32(const void* p) {
    uint32_t a;
    asm("{ .reg .u64 t; cvta.to.shared.u64 t, %1; cvt.u32.u64 %0, t; }" : "=r"(a) : "l"(p));
    return a;
}
__device__ __forceinline__ void cpa16(uint32_t s, const void* g) {
    asm volatile("cp.async.cg.shared.global [%0], [%1], 16;" :: "r"(s), "l"(g));
}
#define CP_COMMIT() asm volatile("cp.async.commit_group;" ::: "memory")
#define CP_WAIT0()  asm volatile("cp.async.wait_group 0;" ::: "memory")

// ---------------- threefry2x32-20 (bit-exact JAX) ---------------------------
__device__ __forceinline__ unsigned rotl32(unsigned v, int d) {
    return (v << d) | (v >> (32 - d));
}
__device__ __forceinline__ void tf2x32(unsigned k0, unsigned k1, unsigned x0, unsigned x1,
                                       unsigned& o0, unsigned& o1) {
    unsigned ks2 = 0x1BD11BDAu ^ k0 ^ k1;
    x0 += k0; x1 += k1;
#define TFR(r) { x0 += x1; x1 = rotl32(x1, (r)); x1 ^= x0; }
    TFR(13) TFR(15) TFR(26) TFR(6)
    x0 += k1; x1 += ks2 + 1u;
    TFR(17) TFR(29) TFR(16) TFR(24)
    x0 += ks2; x1 += k0 + 2u;
    TFR(13) TFR(15) TFR(26) TFR(6)
    x0 += k0; x1 += k1 + 3u;
    TFR(17) TFR(29) TFR(16) TFR(24)
    x0 += k1; x1 += ks2 + 4u;
    TFR(13) TFR(15) TFR(26) TFR(6)
    x0 += ks2; x1 += k0 + 5u;
#undef TFR
    o0 = x0; o1 = x1;
}
__device__ __forceinline__ float jax_uniform_r(int t, int i) {
    unsigned bits;
#if JAX_PARTITIONABLE
    unsigned k0, k1, o0, o1;
    tf2x32(0u, 42u, 0u, (unsigned)t, k0, k1);
    tf2x32(k0, k1, 0u, (unsigned)i, o0, o1);
    bits = o0 ^ o1;
#else
    unsigned k0, k1, a, b;
    {
        int j0 = 2 * t, j1 = 2 * t + 1;
        if (j0 < SL) { tf2x32(0u, 42u, (unsigned)j0, (unsigned)(j0 + SL), a, b); k0 = a; }
        else         { tf2x32(0u, 42u, (unsigned)(j0 - SL), (unsigned)j0, a, b); k0 = b; }
        if (j1 < SL) { tf2x32(0u, 42u, (unsigned)j1, (unsigned)(j1 + SL), a, b); k1 = a; }
        else         { tf2x32(0u, 42u, (unsigned)(j1 - SL), (unsigned)j1, a, b); k1 = b; }
    }
    const int half = (BB * NC) / 2;
    if (i < half) { tf2x32(k0, k1, (unsigned)i, (unsigned)(i + half), a, b); bits = a; }
    else          { tf2x32(k0, k1, (unsigned)(i - half), (unsigned)i, a, b); bits = b; }
#endif
    return __uint_as_float((bits >> 9) | 0x3F800000u) - 1.0f;
}

// ---------------- prep ------------------------------------------------------
__global__ void k_prep(const float* __restrict__ ct1w, const float* __restrict__ ct1b,
                       const float* __restrict__ bn1g, const float* __restrict__ bn1b,
                       const float* __restrict__ bn1m, const float* __restrict__ bn1v,
                       const float* __restrict__ ct2w, const float* __restrict__ ct2b,
                       const float* __restrict__ bn2g, const float* __restrict__ bn2b,
                       const float* __restrict__ bn2m, const float* __restrict__ bn2v,
                       const float* __restrict__ wih1, const float* __restrict__ skel,
                       const float* __restrict__ whh1, const float* __restrict__ bhh1,
                       const float* __restrict__ wih2, const float* __restrict__ bih2,
                       const float* __restrict__ whh2, const float* __restrict__ bhh2) {
    const int nW1 = 128 * 1024, nW2 = 1024 * 512, nW3 = 272 * G3, nWo = G3 * NC;
    const int nWrec = 3 * 512 * G3, nBrec = 3 * G3;
    const int nSk = SL * BB * 16, nB1 = HID, nB2 = 256, nOut = BB * NC;
    int idx = blockIdx.x * blockDim.x + threadIdx.x;
    int r = idx;
    if (r < nW1) {
        int k = r >> 10, n = r & 1023;
        int c = k & 63, o = n & 511, par = n >> 9;
        int t = (k < 64) ? par : par + 2;
        g_W1cat[r] = ct1w[(c * 512 + o) * 4 + t];
        return;
    }
    r -= nW1;
    if (r < nW2) {
        int k = r >> 9, n = r & 511;
        int c = k & 511, o = n & 255, par = n >> 8;
        int t = (k < 512) ? par : par + 2;
        g_W2cat[r] = ct2w[(c * 256 + o) * 4 + t];
        return;
    }
    r -= nW2;
    if (r < nW3) {
        int k = r / G3, j = r % G3;
        float v = 0.f;
        if (k < 256)      v = wih1[j * 274 + 9 + k];
        else if (k < 265) v = wih1[j * 274 + 265 + (k - 256)];
        g_W3[r] = v;
        return;
    }
    r -= nW3;
    if (r < nWo) { g_Wo[r] = wih1[(r / 9) * 274 + (r % 9)]; return; }
    r -= nWo;
    if (r < nWrec) {
        int z = r / (512 * G3), rem = r % (512 * G3);
        int k = rem / G3, n = rem % G3;
        const float* src = (z == 0) ? whh1 : (z == 1 ? wih2 : whh2);
        g_Wrec[r] = src[n * 512 + k];
        return;
    }
    r -= nWrec;
    if (r < nBrec) {
        int z = r / G3, n = r % G3;
        const float* src = (z == 0) ? bhh1 : (z == 1 ? bih2 : bhh2);
        g_brec[r] = src[n];
        return;
    }
    r -= nBrec;
    if (r < nSk) {
        int row = r >> 4, c = r & 15;
        int t = row >> 9, b = row & 511;
        g_SkelP[r] = (c < NC) ? skel[b * (SL * NC) + t * NC + c] : 0.f;
        return;
    }
    r -= nSk;
    if (r < nB1) {
        float s = bn1g[r] * rsqrtf(bn1v[r] + 1e-5f);
        g_bn1s[r] = s;
        g_bn1sh[r] = s * (ct1b[r] - bn1m[r]) + bn1b[r];
        return;
    }
    r -= nB1;
    if (r < nB2) {
        float s = bn2g[r] * rsqrtf(bn2v[r] + 1e-5f);
        g_bn2s[r] = s;
        g_bn2sh[r] = s * (ct2b[r] - bn2m[r]) + bn2b[r];
        return;
    }
    r -= nB2;
    if (r < nOut) g_out[r] = 0.f;
}

// ------------- small GEMM (hfc only): 64x128 tile, 4x8 micro, NT ------------
__global__ __launch_bounds__(256) void k_gemm_nt(
    const float* __restrict__ A, const float* __restrict__ W,
    const float* __restrict__ bias, float* __restrict__ C, int K, int N) {
    __shared__ float As[16][64];
    __shared__ float Ws[16][128];
    int tid = threadIdx.x;
    int tx = tid & 15, ty = tid >> 4;
    int n0 = blockIdx.x * 128, m0 = blockIdx.y * 64;
    float acc[4][8];
#pragma unroll
    for (int i = 0; i < 4; i++)
#pragma unroll
        for (int j = 0; j < 8; j++) acc[i][j] = 0.f;
    for (int k0 = 0; k0 < K; k0 += 16) {
        int arow = tid >> 2, kq = (tid & 3) << 2;
        float4 v = *(const float4*)(A + (size_t)(m0 + arow) * K + k0 + kq);
        As[kq][arow] = v.x; As[kq + 1][arow] = v.y;
        As[kq + 2][arow] = v.z; As[kq + 3][arow] = v.w;
        int nrow = tid >> 1, h = tid & 1;
#pragma unroll
        for (int i = 0; i < 2; i++) {
            int kk = h * 8 + i * 4;
            float4 w = *(const float4*)(W + (size_t)(n0 + nrow) * K + k0 + kk);
            Ws[kk][nrow] = w.x; Ws[kk + 1][nrow] = w.y;
            Ws[kk + 2][nrow] = w.z; Ws[kk + 3][nrow] = w.w;
        }
        __syncthreads();
#pragma unroll
        for (int k = 0; k < 16; k++) {
            float a[4], w[8];
            *(float4*)a = *(const float4*)&As[k][ty * 4];
            *(float4*)w = *(const float4*)&Ws[k][tx * 8];
            *(float4*)(w + 4) = *(const float4*)&Ws[k][tx * 8 + 4];
#pragma unroll
            for (int i = 0; i < 4; i++)
#pragma unroll
                for (int j = 0; j < 8; j++) acc[i][j] += a[i] * w[j];
        }
        __syncthreads();
    }
#pragma unroll
    for (int i = 0; i < 4; i++) {
        int rg = m0 + ty * 4 + i;
#pragma unroll
        for (int j = 0; j < 8; j++) {
            int n = n0 + tx * 8 + j;
            float v = acc[i][j] + bias[n];
            C[(size_t)rg * N + n] = v;
            g_h1T[(size_t)n * BB + rg] = v;   // transposed copy for k_rec
        }
    }
}

// ------------- big prep GEMM: 64x128 tile, 8x8 micro, cp.async W ------------
__device__ __forceinline__ void g2_loadA(const float* A, int K, int amode, int gz,
                                         int m0, int arow, int ak, int k0, float ra[8]) {
    int rg = m0 + arow;
    if (amode == 1) {
#pragma unroll
        for (int i = 0; i < 8; i++) {
            int k = k0 + ak + i;
            int tap = k >> 6, c = k & 63, ii = gz - tap;
            ra[i] = (ii >= 0 && ii < 16) ? A[rg * 1024 + c * 16 + ii] : 0.f;
        }
    } else if (amode == 2) {
        int k = k0 + ak;
        int tap = k >> 9, c = k & 511, ii = gz - tap;
        if (ii >= 0) {
            const float* p = g_y1t + ((size_t)rg * L1 + ii) * 512 + c;
            float4 a0 = *(const float4*)p, a1 = *(const float4*)(p + 4);
            ra[0] = a0.x; ra[1] = a0.y; ra[2] = a0.z; ra[3] = a0.w;
            ra[4] = a1.x; ra[5] = a1.y; ra[6] = a1.z; ra[7] = a1.w;
        } else {
#pragma unroll
            for (int i = 0; i < 8; i++) ra[i] = 0.f;
        }
    } else {
        int k = k0 + ak;
        const float* p = (k < 256) ? (g_Xseq + (size_t)rg * 256 + k)
                                   : (g_SkelP + (size_t)rg * 16 + (k - 256));
        float4 a0 = *(const float4*)p, a1 = *(const float4*)(p + 4);
        ra[0] = a0.x; ra[1] = a0.y; ra[2] = a0.z; ra[3] = a0.w;
        ra[4] = a1.x; ra[5] = a1.y; ra[6] = a1.z; ra[7] = a1.w;
    }
}
__global__ __launch_bounds__(128, 4) void k_gemm2(
    const float* __restrict__ A, const float* __restrict__ W,
    const float* __restrict__ bias, float* __restrict__ C,
    int K, int N, int amode, int emode) {
    __shared__ float As[2][16][68];
    __shared__ float Ws[2][16][128];
    int tid = threadIdx.x;
    int tx = tid & 15, ty = tid >> 4;
    int n0 = blockIdx.x * 128, m0 = blockIdx.y * 64, gz = blockIdx.z;

    unsigned long long acc2[8][4];
#pragma unroll
    for (int i = 0; i < 8; i++)
#pragma unroll
        for (int jp = 0; jp < 4; jp++) acc2[i][jp] = 0ULL;

    int arow = tid >> 1, ak = (tid & 1) * 8;
    int wk = tid >> 4, wn = (tid & 15) * 8;
    float ra[8];
    int nk = K >> 4;
    const uint32_t ws0 = smem_u32(&Ws[0][wk][wn]);
    const uint32_t ws1 = smem_u32(&Ws[1][wk][wn]);
    const float* wbase0 = W + (size_t)wk * N + n0 + wn;
    const float* wbase1 = W + (size_t)(wk + 8) * N + n0 + wn;

#define G2_ISSUEW(k0, buf)                                                        \
    {                                                                             \
        uint32_t s = (buf) ? ws1 : ws0;                                           \
        const float* p0 = wbase0 + (size_t)(k0) * N;                              \
        const float* p1 = wbase1 + (size_t)(k0) * N;                              \
        cpa16(s, p0); cpa16(s + 16, p0 + 4);                                      \
        cpa16(s + 4096, p1); cpa16(s + 4096 + 16, p1 + 4);                        \
        CP_COMMIT();                                                              \
    }
#define G2_STOREA(buf)                                                            \
    {                                                                             \
        _Pragma("unroll")                                                         \
        for (int i = 0; i < 8; i++) As[buf][ak + i][arow] = ra[i];                \
    }

    G2_ISSUEW(0, 0)
    g2_loadA(A, K, amode, gz, m0, arow, ak, 0, ra);
    G2_STOREA(0)
    CP_WAIT0();
    __syncthreads();

    for (int it = 0; it < nk; it++) {
        int cur = it & 1;
        bool more = (it + 1 < nk);
        if (more) {
            G2_ISSUEW((it + 1) << 4, cur ^ 1)
            g2_loadA(A, K, amode, gz, m0, arow, ak, (it + 1) << 4, ra);
        }
#pragma unroll
        for (int k = 0; k < 16; k++) {
            float a[8];
            *(float4*)a = *(const float4*)&As[cur][k][ty * 8];
            *(float4*)(a + 4) = *(const float4*)&As[cur][k][ty * 8 + 4];
            const ulonglong2* wp2 = (const ulonglong2*)&Ws[cur][k][tx * 8];
            ulonglong2 p0 = wp2[0], p1 = wp2[1];
            unsigned long long w2[4] = {p0.x, p0.y, p1.x, p1.y};
#pragma unroll
            for (int i = 0; i < 8; i++) {
                unsigned long long aa = dupf2(a[i]);
#pragma unroll
                for (int jp = 0; jp < 4; jp++) ffma2(acc2[i][jp], aa, w2[jp]);
            }
        }
        if (more) G2_STOREA(cur ^ 1)
        CP_WAIT0();
        __syncthreads();
    }
#undef G2_ISSUEW
#undef G2_STOREA

#pragma unroll
    for (int i = 0; i < 8; i++) {
        int rg = m0 + ty * 8 + i;
        float av[8];
#pragma unroll
        for (int jp = 0; jp < 4; jp++) unpackf2(acc2[i][jp], av[2 * jp], av[2 * jp + 1]);
#pragma unroll
        for (int j = 0; j < 8; j++) {
            int n = n0 + tx * 8 + j;
            float v = av[j];
            if (emode == 0) {
                C[(size_t)rg * N + n] = v + bias[n];
            } else if (emode == 1) {
                int par = n >> 9, o = n & 511, l = 2 * gz + par;
                if (l < L1) {
                    float y = g_bn1s[o] * v + g_bn1sh[o];
                    g_y1t[((size_t)rg * L1 + l) * 512 + o] = (y >= 0.f) ? y : 0.2f * y;
                }
            } else {
                int par = n >> 8, o = n & 255, l = 2 * gz + par;
                float y = g_bn2s[o] * v + g_bn2sh[o];
                g_Xseq[((size_t)l * BB + rg) * 256 + o] = (y >= 0.f) ? y : 0.2f * y;
            }
        }
    }
}

// ------------- recurrence GEMM: all-cp.async (A from h1T/h2T) ---------------
__global__ __launch_bounds__(128, 4) void k_rec() {
    __shared__ float As[2][16][64];
    __shared__ float Ws[2][16][128];
    int tid = threadIdx.x;
    int tx = tid & 15, ty = tid >> 4;
    int n0 = blockIdx.x * 128, m0 = blockIdx.y * 64, gz = blockIdx.z;
    const float* AT = (gz == 2) ? g_h2T : g_h1T;
    const float* W = g_Wrec + (size_t)gz * 512 * G3;
    const float* bias = g_brec + gz * G3;
    float* C = (gz == 0) ? g_gh1 : (gz == 1 ? g_gi2 : g_gh2);

    unsigned long long acc2[8][4];
#pragma unroll
    for (int i = 0; i < 8; i++)
#pragma unroll
        for (int jp = 0; jp < 4; jp++) acc2[i][jp] = 0ULL;

    int wk = tid >> 4, wn = (tid & 15) * 8;
    int arw = tid >> 3, acf = (tid & 7) * 8;    // A: 16 k-rows x 64 m-cols
    const uint32_t ws0 = smem_u32(&Ws[0][wk][wn]);
    const uint32_t ws1 = smem_u32(&Ws[1][wk][wn]);
    const uint32_t as0 = smem_u32(&As[0][arw][acf]);
    const uint32_t as1 = smem_u32(&As[1][arw][acf]);
    const float* wbase0 = W + (size_t)wk * G3 + n0 + wn;
    const float* wbase1 = W + (size_t)(wk + 8) * G3 + n0 + wn;
    const float* abase = AT + (size_t)arw * BB + m0 + acf;

#define R_ISSUE(k0, buf)                                                          \
    {                                                                             \
        uint32_t sw = (buf) ? ws1 : ws0;                                          \
        uint32_t sa = (buf) ? as1 : as0;                                          \
        const float* p0 = wbase0 + (size_t)(k0) * G3;                             \
        const float* p1 = wbase1 + (size_t)(k0) * G3;                             \
        const float* pa = abase + (size_t)(k0) * BB;                              \
        cpa16(sw, p0); cpa16(sw + 16, p0 + 4);                                    \
        cpa16(sw + 4096, p1); cpa16(sw + 4096 + 16, p1 + 4);                      \
        cpa16(sa, pa); cpa16(sa + 16, pa + 4);                                    \
        CP_COMMIT();                                                              \
    }

    R_ISSUE(0, 0)
    CP_WAIT0();
    __syncthreads();

    for (int it = 0; it < 32; it++) {
        int cur = it & 1;
        bool more = (it < 31);
        if (more) R_ISSUE((it + 1) << 4, cur ^ 1)
#pragma unroll
        for (int k = 0; k < 16; k++) {
            float a[8];
            *(float4*)a = *(const float4*)&As[cur][k][ty * 8];
            *(float4*)(a + 4) = *(const float4*)&As[cur][k][ty * 8 + 4];
            const ulonglong2* wp2 = (const ulonglong2*)&Ws[cur][k][tx * 8];
            ulonglong2 p0 = wp2[0], p1 = wp2[1];
            unsigned long long w2[4] = {p0.x, p0.y, p1.x, p1.y};
#pragma unroll
            for (int i = 0; i < 8; i++) {
                unsigned long long aa = dupf2(a[i]);
#pragma unroll
                for (int jp = 0; jp < 4; jp++) ffma2(acc2[i][jp], aa, w2[jp]);
            }
        }
        CP_WAIT0();
        __syncthreads();
    }
#undef R_ISSUE

#pragma unroll
    for (int i = 0; i < 8; i++) {
        int rg = m0 + ty * 8 + i;
        float av[8];
#pragma unroll
        for (int jp = 0; jp < 4; jp++) unpackf2(acc2[i][jp], av[2 * jp], av[2 * jp + 1]);
        float* cp = C + (size_t)rg * G3 + n0 + tx * 8;
        const float* bp = bias + n0 + tx * 8;
#pragma unroll
        for (int j = 0; j < 8; j++) cp[j] = av[j] + bp[j];
    }
}

// ---------------- GRU1 gates (standalone, only for t=0) ---------------------
__global__ __launch_bounds__(512) void k_gates1(int t) {
    __shared__ float os[NC];
    int b = blockIdx.x, j = threadIdx.x;
    if (j < NC) os[j] = g_out[b * NC + j];
    __syncthreads();
    size_t base = ((size_t)t * BB + b) * G3;
    float gi[3], gh[3];
#pragma unroll
    for (int s = 0; s < 3; s++) {
        int jj = j + s * 512;
        float v = g_Gx[base + jj];
        const float* wo = g_Wo + jj * NC;
#pragma unroll
        for (int c = 0; c < NC; c++) v += os[c] * wo[c];
        gi[s] = v;
        gh[s] = g_gh1[b * G3 + jj];
    }
    float h = g_h1[b * 512 + j];
    float rr = 1.f / (1.f + expf(-(gi[0] + gh[0])));
    float zz = 1.f / (1.f + expf(-(gi[1] + gh[1])));
    float nn = tanhf(gi[2] + rr * gh[2]);
    float hn = (1.f - zz) * nn + zz * h;
    g_h1[b * 512 + j] = hn;
    g_h1T[(size_t)j * BB + b] = hn;
    if (t == 0) {
        g_h2[b * 512 + j] = hn;
        g_h2T[(size_t)j * BB + b] = hn;
    }
}

// ------- fused: GRU2(t) + logits + sample + GRU1(t+1) -----------------------
__global__ __launch_bounds__(512) void k_gates21(const float* __restrict__ nfcw,
                                                 const float* __restrict__ nfcb,
                                                 float* __restrict__ out, int t) {
    __shared__ float hs[512];
    __shared__ float os[NC];
    int b = blockIdx.x, j = threadIdx.x;
    float h = g_h2[b * 512 + j];
    float ir = g_gi2[b * G3 + j], iz = g_gi2[b * G3 + 512 + j], in = g_gi2[b * G3 + 1024 + j];
    float hr = g_gh2[b * G3 + j], hz = g_gh2[b * G3 + 512 + j], hn2 = g_gh2[b * G3 + 1024 + j];
    float rr = 1.f / (1.f + expf(-(ir + hr)));
    float zz = 1.f / (1.f + expf(-(iz + hz)));
    float nn = tanhf(in + rr * hn2);
    float hnew = (1.f - zz) * nn + zz * h;
    g_h2[b * 512 + j] = hnew;
    g_h2T[(size_t)j * BB + b] = hnew;
    hs[j] = hnew;
    __syncthreads();
    int w = j >> 5, lane = j & 31;
    if (w < NC) {
        float s = 0.f;
        for (int q = lane; q < 512; q += 32) s += hs[q] * nfcw[w * 512 + q];
#pragma unroll
        for (int o = 16; o; o >>= 1) s += __shfl_down_sync(0xffffffffu, s, o);
        if (lane == 0) {
            float l = s + nfcb[w];
            out[(size_t)b * (SL * NC) + t * NC + w] = l;
            float sg = 1.f / (1.f + expf(-l));
            float r = jax_uniform_r(t, b * NC + w);
            os[w] = (sg - r > 0.f) ? 1.f : 0.f;
        }
    }
    __syncthreads();
    if (t + 1 < SL) {
        size_t base = ((size_t)(t + 1) * BB + b) * G3;
        float gi[3], gh[3];
#pragma unroll
        for (int s = 0; s < 3; s++) {
            int jj = j + s * 512;
            float v = g_Gx[base + jj];
            const float* wo = g_Wo + jj * NC;
#pragma unroll
            for (int c = 0; c < NC; c++) v += os[c] * wo[c];
            gi[s] = v;
            gh[s] = g_gh1[b * G3 + jj];
        }
        float h1 = g_h1[b * 512 + j];
        float r1 = 1.f / (1.f + expf(-(gi[0] + gh[0])));
        float z1 = 1.f / (1.f + expf(-(gi[1] + gh[1])));
        float n1 = tanhf(gi[2] + r1 * gh[2]);
        float h1n = (1.f - z1) * n1 + z1 * h1;
        g_h1[b * 512 + j] = h1n;
        g_h1T[(size_t)j * BB + b] = h1n;
    }
}

// ---------------- host ------------------------------------------------------
extern "C" void kernel_launch(void* const* d_in, const int* in_sizes, int n_in,
                              void* d_out, int out_size) {
    int ofs = (n_in >= 30) ? 0 : -2;
    const float* qz   = (const float*)d_in[0];
    const float* skel = (const float*)d_in[2];
    const float* se   = (const float*)d_in[3];
    const float* ct1w = (const float*)d_in[6 + ofs];
    const float* ct1b = (const float*)d_in[7 + ofs];
    const float* bn1g = (const float*)d_in[8 + ofs];
    const float* bn1b = (const float*)d_in[9 + ofs];
    const float* bn1m = (const float*)d_in[10 + ofs];
    const float* bn1v = (const float*)d_in[11 + ofs];
    const float* ct2w = (const float*)d_in[12 + ofs];
    const float* ct2b = (const float*)d_in[13 + ofs];
    const float* bn2g = (const float*)d_in[14 + ofs];
    const float* bn2b = (const float*)d_in[15 + ofs];
    const float* bn2m = (const float*)d_in[16 + ofs];
    const float* bn2v = (const float*)d_in[17 + ofs];
    const float* hfcw = (const float*)d_in[18 + ofs];
    const float* hfcb = (const float*)d_in[19 + ofs];
    const float* wih1 = (const float*)d_in[20 + ofs];
    const float* whh1 = (const float*)d_in[21 + ofs];
    const float* bih1 = (const float*)d_in[22 + ofs];
    const float* bhh1 = (const float*)d_in[23 + ofs];
    const float* wih2 = (const float*)d_in[24 + ofs];
    const float* whh2 = (const float*)d_in[25 + ofs];
    const float* bih2 = (const float*)d_in[26 + ofs];
    const float* bhh2 = (const float*)d_in[27 + ofs];
    const float* nfcw = (const float*)d_in[28 + ofs];
    const float* nfcb = (const float*)d_in[29 + ofs];
    float* out = (float*)d_out;

    float *pW1, *pW2, *pW3, *pGx, *pH1;
    cudaGetSymbolAddress((void**)&pW1, g_W1cat);
    cudaGetSymbolAddress((void**)&pW2, g_W2cat);
    cudaGetSymbolAddress((void**)&pW3, g_W3);
    cudaGetSymbolAddress((void**)&pGx, g_Gx);
    cudaGetSymbolAddress((void**)&pH1, g_h1);

    const int TOTAL = 128 * 1024 + 1024 * 512 + 272 * G3 + G3 * NC +
                      3 * 512 * G3 + 3 * G3 +
                      SL * BB * 16 + HID + 256 + BB * NC;
    k_prep<<<(TOTAL + 255) / 256, 256>>>(ct1w, ct1b, bn1g, bn1b, bn1m, bn1v,
                                         ct2w, ct2b, bn2g, bn2b, bn2m, bn2v,
                                         wih1, skel,
                                         whh1, bhh1, wih2, bih2, whh2, bhh2);
    k_gemm_nt<<<dim3(4, 8, 1), 256>>>(se, hfcw, hfcb, pH1, 512, 512);
    k_gemm2<<<dim3(8, 8, 18), 128>>>(qz, pW1, nullptr, nullptr, 128, 1024, 1, 1);
    k_gemm2<<<dim3(4, 8, 32), 128>>>(nullptr, pW2, nullptr, nullptr, 1024, 512, 2, 2);
    k_gemm2<<<dim3(12, 512, 1), 128>>>(nullptr, pW3, bih1, pGx, 272, G3, 3, 0);
    k_rec<<<dim3(12, 8, 1), 128>>>();        // gh1(0)
    k_gates1<<<BB, 512>>>(0);                // GRU1 step 0

    for (int t = 0; t < SL; t++) {
        k_rec<<<dim3(12, 8, 3), 128>>>();    // 288 blocks, 4/SM resident
        k_gates21<<<BB, 512>>>(nfcw, nfcb, out, t);
    }
}